// round 2
// baseline (speedup 1.0000x reference)
#include <cuda_runtime.h>

// Problem constants
#define NQ 32768          // B*H*W = 32*32*32 queries
#define KC 1024           // codebook entries
#define DD 256            // embedding dim
#define ZQ_ELEMS 8388608  // 32*256*32*32

// GEMM tiling
#define BM 128
#define BN 128
#define BK 16

// Scratch (device globals: allocation-free rule)
__device__ float g_cnorm[KC];
__device__ int   g_idx[NQ];
__device__ float g_part[256];

// ---------------------------------------------------------------------------
// Kernel 1: codebook row norms, sequential fp32 sum (mirror jax rounding style)
// ---------------------------------------------------------------------------
__global__ void cnorm_kernel(const float* __restrict__ cb) {
    int k = blockIdx.x * blockDim.x + threadIdx.x;
    if (k < KC) {
        const float* row = cb + (size_t)k * DD;
        float s = 0.f;
        for (int d = 0; d < DD; ++d) {
            float v = row[d];
            s = __fadd_rn(s, __fmul_rn(v, v));
        }
        g_cnorm[k] = s;
    }
}

// ---------------------------------------------------------------------------
// Kernel 2: fused distance GEMM + argmin.
// Each block: 128 queries (contiguous hw within one b) x all 1024 codes.
// score = fl( fl(znorm + cnorm) - fl(2*dot) )  -- matches jax expression shape.
// Tie-break: first (lowest) index, exactly like jnp.argmin.
// ---------------------------------------------------------------------------
__global__ __launch_bounds__(256) void argmin_kernel(
        const float* __restrict__ z, const float* __restrict__ cb) {
    __shared__ float As[BK][BM];      // As[d][m]
    __shared__ float Bs[BK][BN];      // Bs[d][k]
    __shared__ float zn_s[BM];
    __shared__ float cn_s[BN];
    __shared__ float red[256];

    const int t   = threadIdx.x;
    const int n0  = blockIdx.x * BM;
    const int b   = n0 >> 10;         // 1024 hw per image
    const int hw0 = n0 & 1023;
    const int tx  = t & 15;
    const int ty  = t >> 4;

    // ---- query norms: 2 threads per query, each sums 128 channels ----
    {
        const int q = t & 127, half = t >> 7;
        const float* base = z + ((size_t)(b * 256 + half * 128)) * 1024 + hw0 + q;
        float s = 0.f;
        #pragma unroll 4
        for (int d = 0; d < 128; ++d) {
            float v = base[(size_t)d * 1024];
            s = __fadd_rn(s, __fmul_rn(v, v));
        }
        red[t] = s;
        __syncthreads();
        if (t < 128) zn_s[t] = __fadd_rn(red[t], red[t + 128]);
    }

    float bestv[8];
    int   besti[8];
    #pragma unroll
    for (int i = 0; i < 8; ++i) { bestv[i] = 3.4e38f; besti[i] = 0; }

    for (int kn = 0; kn < KC / BN; ++kn) {     // 8 code tiles, ascending k
        __syncthreads();                        // previous epilogue done
        if (t < 128) cn_s[t] = g_cnorm[kn * 128 + t];

        float acc[8][8];
        #pragma unroll
        for (int i = 0; i < 8; ++i)
            #pragma unroll
            for (int j = 0; j < 8; ++j) acc[i][j] = 0.f;

        for (int kt = 0; kt < DD / BK; ++kt) {  // 16 depth chunks
            __syncthreads();
            // Load A tile: As[dd][m] = z[(b*256 + kt*16+dd)*1024 + hw0 + m]
            #pragma unroll
            for (int i = 0; i < 2; ++i) {
                int lin = t + 256 * i;          // 512 float4s
                int dd  = lin >> 5;
                int m4  = (lin & 31) << 2;
                float4 v = *reinterpret_cast<const float4*>(
                    z + ((size_t)(b * 256 + kt * 16 + dd)) * 1024 + hw0 + m4);
                *reinterpret_cast<float4*>(&As[dd][m4]) = v;
            }
            // Load B tile (transpose): Bs[dd][k] = cb[(kn*128+k)*256 + kt*16+dd]
            {
                int kcol = t & 127, half = t >> 7;
                const float* src = cb + ((size_t)(kn * 128 + kcol)) * DD
                                      + kt * 16 + half * 8;
                float4 v0 = *reinterpret_cast<const float4*>(src);
                float4 v1 = *reinterpret_cast<const float4*>(src + 4);
                int d0 = half * 8;
                Bs[d0 + 0][kcol] = v0.x; Bs[d0 + 1][kcol] = v0.y;
                Bs[d0 + 2][kcol] = v0.z; Bs[d0 + 3][kcol] = v0.w;
                Bs[d0 + 4][kcol] = v1.x; Bs[d0 + 5][kcol] = v1.y;
                Bs[d0 + 6][kcol] = v1.z; Bs[d0 + 7][kcol] = v1.w;
            }
            __syncthreads();

            #pragma unroll
            for (int dd = 0; dd < BK; ++dd) {
                float a[8], bb[8];
                #pragma unroll
                for (int i = 0; i < 8; ++i) a[i]  = As[dd][ty + 16 * i];
                #pragma unroll
                for (int j = 0; j < 8; ++j) bb[j] = Bs[dd][tx + 16 * j];
                #pragma unroll
                for (int i = 0; i < 8; ++i)
                    #pragma unroll
                    for (int j = 0; j < 8; ++j)
                        acc[i][j] = fmaf(a[i], bb[j], acc[i][j]);
            }
        }

        // Epilogue: fold norms, track running min (k ascending within thread)
        #pragma unroll
        for (int i = 0; i < 8; ++i) {
            float zn = zn_s[ty + 16 * i];
            #pragma unroll
            for (int j = 0; j < 8; ++j) {
                float t1 = __fadd_rn(zn, cn_s[tx + 16 * j]);
                float sc = __fadd_rn(t1, __fmul_rn(-2.0f, acc[i][j]));
                int   k  = kn * 128 + tx + 16 * j;
                if (sc < bestv[i]) { bestv[i] = sc; besti[i] = k; }
            }
        }
    }

    // Cross-thread reduce over the 16 tx lanes (lanes are contiguous in warp)
    #pragma unroll
    for (int i = 0; i < 8; ++i) {
        float v  = bestv[i];
        int   id = besti[i];
        #pragma unroll
        for (int off = 8; off >= 1; off >>= 1) {
            float v2 = __shfl_down_sync(0xffffffffu, v,  off, 16);
            int   i2 = __shfl_down_sync(0xffffffffu, id, off, 16);
            if (v2 < v || (v2 == v && i2 < id)) { v = v2; id = i2; }
        }
        if (tx == 0) g_idx[n0 + ty + 16 * i] = id;
    }
}

// ---------------------------------------------------------------------------
// Kernel 3: gather z_q (NCHW layout via smem transpose), write indices,
// accumulate per-block squared-error partials (deterministic slots).
// ---------------------------------------------------------------------------
__global__ __launch_bounds__(256) void gather_kernel(
        const float* __restrict__ z, const float* __restrict__ cb,
        float* __restrict__ out_zq, float* __restrict__ out_idxf) {
    __shared__ float tile[32][129];
    __shared__ int   idx_s[128];
    __shared__ float red[256];

    const int t   = threadIdx.x;
    const int n0  = blockIdx.x * 128;
    const int b   = n0 >> 10;
    const int hw0 = n0 & 1023;

    if (t < 128) {
        int id = g_idx[n0 + t];
        idx_s[t] = id;
        out_idxf[n0 + t] = (float)id;
    }
    __syncthreads();

    float lsum = 0.f;
    for (int c0 = 0; c0 < DD; c0 += 32) {
        // gather: 2 threads per query, 16 channels each, coalesced row reads
        {
            int q = t >> 1, part = t & 1;
            const float* src = cb + (size_t)idx_s[q] * DD + c0 + part * 16;
            #pragma unroll
            for (int u = 0; u < 4; ++u) {
                float4 v = *reinterpret_cast<const float4*>(src + u * 4);
                int cc = part * 16 + u * 4;
                tile[cc + 0][q] = v.x; tile[cc + 1][q] = v.y;
                tile[cc + 2][q] = v.z; tile[cc + 3][q] = v.w;
            }
        }
        __syncthreads();
        // write: contiguous 128-float rows per channel, coalesced
        #pragma unroll
        for (int i = 0; i < 16; ++i) {
            int lin = t + 256 * i;
            int cc  = lin >> 7;
            int q   = lin & 127;
            size_t g = ((size_t)(b * 256 + c0 + cc)) * 1024 + hw0 + q;
            float v  = tile[cc][q];
            out_zq[g] = v;
            float dv = v - z[g];
            lsum = fmaf(dv, dv, lsum);
        }
        __syncthreads();
    }

    red[t] = lsum;
    __syncthreads();
    for (int s = 128; s > 0; s >>= 1) {
        if (t < s) red[t] += red[t + s];
        __syncthreads();
    }
    if (t == 0) g_part[blockIdx.x] = red[0];
}

// ---------------------------------------------------------------------------
// Kernel 4: finalize loss = (1 + 0.25) * mean((z_q - z)^2)
// ---------------------------------------------------------------------------
__global__ void loss_kernel(float* __restrict__ out_loss) {
    __shared__ float red[256];
    int t = threadIdx.x;
    red[t] = g_part[t];
    __syncthreads();
    for (int s = 128; s > 0; s >>= 1) {
        if (t < s) red[t] += red[t + s];
        __syncthreads();
    }
    if (t == 0) out_loss[0] = 1.25f * red[0] / (float)ZQ_ELEMS;
}

// ---------------------------------------------------------------------------
extern "C" void kernel_launch(void* const* d_in, const int* in_sizes, int n_in,
                              void* d_out, int out_size) {
    const float* z  = (const float*)d_in[0];   // [32,256,32,32]
    const float* cb = (const float*)d_in[1];   // [1024,256]
    float* out      = (float*)d_out;
    float* out_zq   = out;                     // 8388608 elems
    float* out_loss = out + ZQ_ELEMS;          // 1 elem
    float* out_idxf = out + ZQ_ELEMS + 1;      // 32768 elems (indices as f32)

    cnorm_kernel<<<4, 256>>>(cb);
    argmin_kernel<<<NQ / BM, 256>>>(z, cb);
    gather_kernel<<<NQ / 128, 256>>>(z, cb, out_zq, out_idxf);
    loss_kernel<<<1, 256>>>(out_loss);
}